// round 8
// baseline (speedup 1.0000x reference)
#include <cuda_runtime.h>
#include <cstdint>
#include <cstddef>

#define T_STEPS 1024
#define BATCH   64
#define DDIM    128
#define HDIM    512
#define ALPHA   0.1f

#define CLUSTER 8
#define BPC     4
#define NTHR    512

#define ABUF_FLOATS  2560                 // [k(640)][b(4)] ; k<512 fr (8 rotated
                                          // 64-g positions), k>=512 x
#define SA_FLOATS    (2 * ABUF_FLOATS)    // ping-pong
#define MBAR_OFF     SA_FLOATS            // float idx; 8B aligned
#define SMEM_BYTES   ((MBAR_OFF + 8) * 4)

#define TX_BYTES 7168                     // 7 peers x 16 warps x 64B

// ---- packed fp32x2 helpers ----
__device__ __forceinline__ unsigned long long fma2(unsigned long long a,
                                                   unsigned long long b,
                                                   unsigned long long c) {
    unsigned long long d;
    asm("fma.rn.f32x2 %0, %1, %2, %3;" : "=l"(d) : "l"(a), "l"(b), "l"(c));
    return d;
}
__device__ __forceinline__ unsigned long long splat2(float x) {
    unsigned long long d;
    asm("mov.b64 %0, {%1, %1};" : "=l"(d) : "f"(x));
    return d;
}
__device__ __forceinline__ unsigned long long pack2(float lo, float hi) {
    unsigned long long d;
    asm("mov.b64 %0, {%1, %2};" : "=l"(d) : "f"(lo), "f"(hi));
    return d;
}
__device__ __forceinline__ float lo32(unsigned long long v) {
    return __uint_as_float((unsigned)(v & 0xFFFFFFFFull));
}
__device__ __forceinline__ float hi32(unsigned long long v) {
    return __uint_as_float((unsigned)(v >> 32));
}

// ---- cluster / mbarrier helpers ----
__device__ __forceinline__ unsigned mapa_u32(unsigned addr, unsigned rank) {
    unsigned d;
    asm("mapa.shared::cluster.u32 %0, %1, %2;" : "=r"(d) : "r"(addr), "r"(rank));
    return d;
}
__device__ __forceinline__ void mbar_init(unsigned addr, unsigned cnt) {
    asm volatile("mbarrier.init.shared.b64 [%0], %1;" :: "r"(addr), "r"(cnt) : "memory");
}
__device__ __forceinline__ void mbar_arrive_expect_tx(unsigned addr, unsigned bytes) {
    asm volatile("mbarrier.arrive.expect_tx.shared.b64 _, [%0], %1;"
                 :: "r"(addr), "r"(bytes) : "memory");
}
__device__ __forceinline__ void mbar_wait_parity(unsigned addr, unsigned parity) {
    unsigned done;
    asm volatile(
        "{\n\t.reg .pred p;\n\t"
        "mbarrier.try_wait.parity.acquire.cta.shared::cta.b64 p, [%1], %2;\n\t"
        "selp.b32 %0, 1, 0, p;\n\t}"
        : "=r"(done) : "r"(addr), "r"(parity) : "memory");
    if (!done) {
        asm volatile(
            "{\n\t.reg .pred P1;\n\t"
            "WAIT_LOOP_%=:\n\t"
            "mbarrier.try_wait.parity.acquire.cta.shared::cta.b64 P1, [%0], %1, 0x989680;\n\t"
            "@P1 bra.uni WAIT_DONE_%=;\n\t"
            "bra.uni WAIT_LOOP_%=;\n\t"
            "WAIT_DONE_%=:\n\t}"
            :: "r"(addr), "r"(parity) : "memory");
    }
}
__device__ __forceinline__ void bulk_dsmem(unsigned dst_cluster, unsigned src_cta,
                                           unsigned bytes, unsigned mbar_cluster) {
    asm volatile(
        "cp.async.bulk.shared::cluster.shared::cta.mbarrier::complete_tx::bytes "
        "[%0], [%1], %2, [%3];"
        :: "r"(dst_cluster), "r"(src_cta), "r"(bytes), "r"(mbar_cluster) : "memory");
}
__device__ __forceinline__ void fence_proxy_async_cta() {
    asm volatile("fence.proxy.async.shared::cta;" ::: "memory");
}
__device__ __forceinline__ void cluster_sync_() {
    asm volatile("barrier.cluster.arrive.aligned;" ::: "memory");
    asm volatile("barrier.cluster.wait.aligned;" ::: "memory");
}

__global__ void __launch_bounds__(NTHR, 1)
rnn_kernel(const float* __restrict__ input, const float* __restrict__ Win,
           const float* __restrict__ bin,   const float* __restrict__ Whid,
           const float* __restrict__ bhid,  float* __restrict__ out)
{
    extern __shared__ float sA[];   // [2][640][4] | mbar[2]

    const int tid  = threadIdx.x;
    const int lane = tid & 31;
    const int w    = tid >> 5;
    const int bx   = blockIdx.x;
    const int rank = bx & (CLUSTER - 1);
    const int cl   = bx >> 3;
    const int b0   = cl * BPC;
    const int g0   = rank * 64;
    const int gbase = g0 + w * 4;

    // lane's output after the butterfly (verified mapping):
    const int vidx = ((lane >> 4) & 1) * 8 + ((lane >> 3) & 1) * 4
                   + ((lane >> 2) & 1) * 2 + ((lane >> 1) & 1);
    const int gl = vidx >> 2;
    const int bb = vidx & 3;
    const int hmine = gbase + gl;

    // ---- W into registers, permuted to ROTATED BUFFER LAYOUT ----
    // Buffer position p (chunks 2p, 2p+1) holds slice of rank (rank+1+p)&7
    // for p<7; position 7 (chunks 14,15) holds OWN slice. Register indices
    // are static; only the gmem load address depends on rank.
    unsigned long long wA[20], wB[20];
    #pragma unroll
    for (int j = 0; j < 16; ++j) {
        int p  = j >> 1;
        int rr = (p < 7) ? ((rank + 1 + p) & 7) : rank;
        int h  = rr * 64 + (j & 1) * 32 + lane;
        wA[j] = pack2(ALPHA * Whid[(gbase + 0) * HDIM + h],
                      ALPHA * Whid[(gbase + 1) * HDIM + h]);
        wB[j] = pack2(ALPHA * Whid[(gbase + 2) * HDIM + h],
                      ALPHA * Whid[(gbase + 3) * HDIM + h]);
    }
    #pragma unroll
    for (int j = 16; j < 20; ++j) {
        int k = (j - 16) * 32 + lane;
        wA[j] = pack2(ALPHA * Win[(gbase + 0) * DDIM + k],
                      ALPHA * Win[(gbase + 1) * DDIM + k]);
        wB[j] = pack2(ALPHA * Win[(gbase + 2) * DDIM + k],
                      ALPHA * Win[(gbase + 3) * DDIM + k]);
    }
    const float breg = ALPHA * (bhid[hmine] + bin[hmine]);
    float vreg = 0.0f;

    const unsigned smemBase = (unsigned)__cvta_generic_to_shared(sA);
    const unsigned mbarBase = smemBase + MBAR_OFF * 4;

    // ---- init: buffer0 fr = 0 ; x = input[t=0]; arm both mbars ----
    {
        float4 z = {0.f, 0.f, 0.f, 0.f};
        ((float4*)sA)[tid] = z;
        int d = w * 8 + (lane >> 2);
        int b = lane & 3;
        sA[(HDIM + d) * 4 + b] = input[(size_t)(b0 + b) * DDIM + d];
    }
    if (tid == 0) {
        mbar_init(mbarBase + 0, 1);
        mbar_init(mbarBase + 8, 1);
        mbar_arrive_expect_tx(mbarBase + 0, TX_BYTES);
        mbar_arrive_expect_tx(mbarBase + 8, TX_BYTES);
    }
    __syncthreads();
    cluster_sync_();   // mbars live before any peer bulk-copy can land

    const int xd = w * 8 + (lane >> 2);
    const int xb = lane & 3;

    #define GEMM_STEP(KIDX, KK)                                                \
        {                                                                      \
            float4 a4 = *(const float4*)&aBuf[(KIDX) * 4];                     \
            unsigned long long s0 = splat2(a4.x), s1 = splat2(a4.y);           \
            unsigned long long s2 = splat2(a4.z), s3 = splat2(a4.w);           \
            acc[0] = fma2(wA[KK], s0, acc[0]); acc[1] = fma2(wB[KK], s0, acc[1]);\
            acc[2] = fma2(wA[KK], s1, acc[2]); acc[3] = fma2(wB[KK], s1, acc[3]);\
            acc[4] = fma2(wA[KK], s2, acc[4]); acc[5] = fma2(wB[KK], s2, acc[5]);\
            acc[6] = fma2(wA[KK], s3, acc[6]); acc[7] = fma2(wB[KK], s3, acc[7]);\
        }

    // ---- prologue: own chunks (zeros) + x chunks, on buffer 0 ----
    unsigned long long acc[8];
    #pragma unroll
    for (int i = 0; i < 8; ++i) acc[i] = 0ull;
    {
        const float* aBuf = sA;
        GEMM_STEP(14 * 32 + lane, 14)
        GEMM_STEP(15 * 32 + lane, 15)
        #pragma unroll
        for (int j = 16; j < 20; ++j)
            GEMM_STEP(HDIM + (j - 16) * 32 + lane, j)
    }

    int ph0 = 0, ph1 = 0;
    int cur = 0;
    for (int t = 0; t < T_STEPS; ++t) {
        // ---- wait for 7 peers' fr(t); re-arm for t+2 ----
        if (t > 0) {
            unsigned mb = mbarBase + (unsigned)(cur * 8);
            unsigned par = (unsigned)(cur ? ph1 : ph0);
            mbar_wait_parity(mb, par);
            if (cur) ph1 ^= 1; else ph0 ^= 1;
            if (tid == 0) mbar_arrive_expect_tx(mb, TX_BYTES);
        }

        // prefetch x(t+1) — hidden under main GEMM
        float xv = 0.f;
        if (t + 1 < T_STEPS)
            xv = input[((size_t)(t + 1) * BATCH + b0 + xb) * DDIM + xd];

        const float* aBuf = sA + cur * ABUF_FLOATS;

        // ---- main GEMM: peer chunks 0..13, all-static addressing ----
        #pragma unroll
        for (int j = 0; j < 14; ++j)
            GEMM_STEP(j * 32 + lane, j)

        // ---- unpack + warp butterfly (16 outputs over 32 lanes) ----
        float v[16];
        #pragma unroll
        for (int b = 0; b < 4; ++b) {
            v[0 * 4 + b] = lo32(acc[2 * b]);
            v[1 * 4 + b] = hi32(acc[2 * b]);
            v[2 * 4 + b] = lo32(acc[2 * b + 1]);
            v[3 * 4 + b] = hi32(acc[2 * b + 1]);
        }
        #pragma unroll
        for (int s = 16, cnt = 16; s >= 2; s >>= 1, cnt >>= 1) {
            const bool up = (lane & s) != 0;
            const int half = cnt >> 1;
            #pragma unroll
            for (int i = 0; i < 8; ++i) {
                if (i >= half) break;
                float keep = up ? v[i + half] : v[i];
                float send = up ? v[i] : v[i + half];
                float got  = __shfl_xor_sync(0xFFFFFFFFu, send, s);
                v[i] = keep + got;
            }
        }
        v[0] += __shfl_xor_sync(0xFFFFFFFFu, v[0], 1);

        // ---- leaky update + relu ----
        vreg = (1.0f - ALPHA) * vreg + (v[0] + breg);
        float fr = fmaxf(vreg, 0.f);
        if ((lane & 1) == 0)
            out[((size_t)t * BATCH + b0 + bb) * HDIM + hmine] = fr;

        if (t + 1 < T_STEPS) {
            const int nxt = cur ^ 1;
            float* nbuf = sA + nxt * ABUF_FLOATS;

            // gather 4 batch values per g; write own POSITION-7 slice
            float frb1 = __shfl_xor_sync(0xFFFFFFFFu, fr, 2);
            unsigned long long p01 = pack2(fr, frb1);
            unsigned long long p23 = __shfl_xor_sync(0xFFFFFFFFu, p01, 4);
            if ((lane & 7) == 0) {
                int lg = w * 4 + (lane >> 3);      // local g 0..63
                *(float4*)&nbuf[(448 + lg) * 4] =
                    make_float4(lo32(p01), hi32(p01), lo32(p23), hi32(p23));
            }
            // stage x(t+1)
            nbuf[(HDIM + xd) * 4 + xb] = xv;

            // ---- per-warp EAGER push: this warp's 64B to 7 peers ----
            __syncwarp();
            if (lane == 0) {
                fence_proxy_async_cta();
                unsigned src = smemBase
                    + (unsigned)((nxt * ABUF_FLOATS + (448 + w * 4) * 4) * 4);
                unsigned mOff = mbarBase + (unsigned)(nxt * 8);
                #pragma unroll
                for (int pp = 0; pp < 7; ++pp) {
                    unsigned c = (unsigned)pp + ((pp >= rank) ? 1u : 0u);
                    unsigned p = (unsigned)(rank - (int)c - 1) & 7u;
                    unsigned dst = smemBase
                        + (unsigned)((nxt * ABUF_FLOATS + (p * 64 + w * 4) * 4) * 4);
                    bulk_dsmem(mapa_u32(dst, c), src, 64, mapa_u32(mOff, c));
                }
            }

            __syncthreads();   // own pos-7 slice + x visible for prewait

            // ---- prewait GEMM for t+1: own chunks 14,15 + x 16..19 ----
            #pragma unroll
            for (int i = 0; i < 8; ++i) acc[i] = 0ull;
            {
                const float* aBuf = nbuf;
                GEMM_STEP(14 * 32 + lane, 14)
                GEMM_STEP(15 * 32 + lane, 15)
                #pragma unroll
                for (int j = 16; j < 20; ++j)
                    GEMM_STEP(HDIM + (j - 16) * 32 + lane, j)
            }
        }
        cur ^= 1;
    }
}

extern "C" void kernel_launch(void* const* d_in, const int* in_sizes, int n_in,
                              void* d_out, int out_size)
{
    const float* input = (const float*)d_in[0];
    const float* Win   = (const float*)d_in[1];
    const float* bin   = (const float*)d_in[2];
    const float* Whid  = (const float*)d_in[3];
    const float* bhid  = (const float*)d_in[4];
    float* out = (float*)d_out;

    cudaFuncSetAttribute(rnn_kernel,
                         cudaFuncAttributeMaxDynamicSharedMemorySize, SMEM_BYTES);

    cudaLaunchConfig_t cfg = {};
    cfg.gridDim  = dim3(16 * CLUSTER, 1, 1);
    cfg.blockDim = dim3(NTHR, 1, 1);
    cfg.dynamicSmemBytes = SMEM_BYTES;
    cfg.stream = 0;

    cudaLaunchAttribute attr[1];
    attr[0].id = cudaLaunchAttributeClusterDimension;
    attr[0].val.clusterDim.x = CLUSTER;
    attr[0].val.clusterDim.y = 1;
    attr[0].val.clusterDim.z = 1;
    cfg.attrs = attr;
    cfg.numAttrs = 1;

    cudaLaunchKernelEx(&cfg, rnn_kernel, input, Win, bin, Whid, bhid, out);
}

// round 9
// speedup vs baseline: 1.2816x; 1.2816x over previous
#include <cuda_runtime.h>
#include <cstdint>
#include <cstddef>

#define T_STEPS 1024
#define BATCH   64
#define DDIM    128
#define HDIM    512
#define ALPHA   0.1f

#define CLUSTER 8
#define BPC     4
#define NTHR    512

#define ABUF_FLOATS  2560                 // [k(640)][b(4)] ; k<512 fr (8 rotated
                                          // 64-g positions), k>=512 x
#define SA_FLOATS    (2 * ABUF_FLOATS)    // ping-pong
#define MBAR_OFF     SA_FLOATS            // float idx; 8B aligned
#define SMEM_BYTES   ((MBAR_OFF + 8) * 4)

#define TX_BYTES 7168                     // 7 peers x 1KB

// ---- packed fp32x2 helpers ----
__device__ __forceinline__ unsigned long long fma2(unsigned long long a,
                                                   unsigned long long b,
                                                   unsigned long long c) {
    unsigned long long d;
    asm("fma.rn.f32x2 %0, %1, %2, %3;" : "=l"(d) : "l"(a), "l"(b), "l"(c));
    return d;
}
__device__ __forceinline__ unsigned long long splat2(float x) {
    unsigned long long d;
    asm("mov.b64 %0, {%1, %1};" : "=l"(d) : "f"(x));
    return d;
}
__device__ __forceinline__ unsigned long long pack2(float lo, float hi) {
    unsigned long long d;
    asm("mov.b64 %0, {%1, %2};" : "=l"(d) : "f"(lo), "f"(hi));
    return d;
}
__device__ __forceinline__ float lo32(unsigned long long v) {
    return __uint_as_float((unsigned)(v & 0xFFFFFFFFull));
}
__device__ __forceinline__ float hi32(unsigned long long v) {
    return __uint_as_float((unsigned)(v >> 32));
}

// ---- cluster / mbarrier helpers ----
__device__ __forceinline__ unsigned mapa_u32(unsigned addr, unsigned rank) {
    unsigned d;
    asm("mapa.shared::cluster.u32 %0, %1, %2;" : "=r"(d) : "r"(addr), "r"(rank));
    return d;
}
__device__ __forceinline__ void mbar_init(unsigned addr, unsigned cnt) {
    asm volatile("mbarrier.init.shared.b64 [%0], %1;" :: "r"(addr), "r"(cnt) : "memory");
}
__device__ __forceinline__ void mbar_arrive_expect_tx(unsigned addr, unsigned bytes) {
    asm volatile("mbarrier.arrive.expect_tx.shared.b64 _, [%0], %1;"
                 :: "r"(addr), "r"(bytes) : "memory");
}
__device__ __forceinline__ void mbar_wait_parity(unsigned addr, unsigned parity) {
    unsigned done;
    asm volatile(
        "{\n\t.reg .pred p;\n\t"
        "mbarrier.try_wait.parity.acquire.cta.shared::cta.b64 p, [%1], %2;\n\t"
        "selp.b32 %0, 1, 0, p;\n\t}"
        : "=r"(done) : "r"(addr), "r"(parity) : "memory");
    if (!done) {
        asm volatile(
            "{\n\t.reg .pred P1;\n\t"
            "WAIT_LOOP_%=:\n\t"
            "mbarrier.try_wait.parity.acquire.cta.shared::cta.b64 P1, [%0], %1, 0x989680;\n\t"
            "@P1 bra.uni WAIT_DONE_%=;\n\t"
            "bra.uni WAIT_LOOP_%=;\n\t"
            "WAIT_DONE_%=:\n\t}"
            :: "r"(addr), "r"(parity) : "memory");
    }
}
__device__ __forceinline__ void bulk_dsmem(unsigned dst_cluster, unsigned src_cta,
                                           unsigned bytes, unsigned mbar_cluster) {
    asm volatile(
        "cp.async.bulk.shared::cluster.shared::cta.mbarrier::complete_tx::bytes "
        "[%0], [%1], %2, [%3];"
        :: "r"(dst_cluster), "r"(src_cta), "r"(bytes), "r"(mbar_cluster) : "memory");
}
__device__ __forceinline__ void fence_proxy_async_cta() {
    asm volatile("fence.proxy.async.shared::cta;" ::: "memory");
}
__device__ __forceinline__ void cluster_sync_() {
    asm volatile("barrier.cluster.arrive.aligned;" ::: "memory");
    asm volatile("barrier.cluster.wait.aligned;" ::: "memory");
}

__global__ void __launch_bounds__(NTHR, 1)
rnn_kernel(const float* __restrict__ input, const float* __restrict__ Win,
           const float* __restrict__ bin,   const float* __restrict__ Whid,
           const float* __restrict__ bhid,  float* __restrict__ out)
{
    extern __shared__ float sA[];   // [2][640][4] | mbar[2]

    const int tid  = threadIdx.x;
    const int lane = tid & 31;
    const int w    = tid >> 5;
    const int bx   = blockIdx.x;
    const int rank = bx & (CLUSTER - 1);
    const int cl   = bx >> 3;
    const int b0   = cl * BPC;
    const int g0   = rank * 64;
    const int gbase = g0 + w * 4;

    // lane's output after the butterfly (verified mapping):
    const int vidx = ((lane >> 4) & 1) * 8 + ((lane >> 3) & 1) * 4
                   + ((lane >> 2) & 1) * 2 + ((lane >> 1) & 1);
    const int gl = vidx >> 2;
    const int bb = vidx & 3;
    const int hmine = gbase + gl;

    // ---- W into registers, permuted to ROTATED BUFFER LAYOUT ----
    // Buffer position p (chunks 2p, 2p+1) holds slice of rank (rank+1+p)&7
    // for p<7; position 7 (chunks 14,15) holds OWN slice. Register indices
    // are static; only the gmem load address depends on rank.
    unsigned long long wA[20], wB[20];
    #pragma unroll
    for (int j = 0; j < 16; ++j) {
        int p  = j >> 1;
        int rr = (p < 7) ? ((rank + 1 + p) & 7) : rank;
        int h  = rr * 64 + (j & 1) * 32 + lane;
        wA[j] = pack2(ALPHA * Whid[(gbase + 0) * HDIM + h],
                      ALPHA * Whid[(gbase + 1) * HDIM + h]);
        wB[j] = pack2(ALPHA * Whid[(gbase + 2) * HDIM + h],
                      ALPHA * Whid[(gbase + 3) * HDIM + h]);
    }
    #pragma unroll
    for (int j = 16; j < 20; ++j) {
        int k = (j - 16) * 32 + lane;
        wA[j] = pack2(ALPHA * Win[(gbase + 0) * DDIM + k],
                      ALPHA * Win[(gbase + 1) * DDIM + k]);
        wB[j] = pack2(ALPHA * Win[(gbase + 2) * DDIM + k],
                      ALPHA * Win[(gbase + 3) * DDIM + k]);
    }
    const float breg = ALPHA * (bhid[hmine] + bin[hmine]);
    float vreg = 0.0f;

    const unsigned smemBase = (unsigned)__cvta_generic_to_shared(sA);
    const unsigned mbarBase = smemBase + MBAR_OFF * 4;

    // ---- init: buffer0 fr = 0 ; x = input[t=0]; arm both mbars ----
    {
        float4 z = {0.f, 0.f, 0.f, 0.f};
        ((float4*)sA)[tid] = z;
        int d = w * 8 + (lane >> 2);
        int b = lane & 3;
        sA[(HDIM + d) * 4 + b] = input[(size_t)(b0 + b) * DDIM + d];
    }
    if (tid == 0) {
        mbar_init(mbarBase + 0, 1);
        mbar_init(mbarBase + 8, 1);
        mbar_arrive_expect_tx(mbarBase + 0, TX_BYTES);
        mbar_arrive_expect_tx(mbarBase + 8, TX_BYTES);
    }
    __syncthreads();
    cluster_sync_();   // mbars live before any peer bulk-copy can land

    const int xd = w * 8 + (lane >> 2);
    const int xb = lane & 3;

    #define GEMM_STEP(KIDX, KK)                                                \
        {                                                                      \
            float4 a4 = *(const float4*)&aBuf[(KIDX) * 4];                     \
            unsigned long long s0 = splat2(a4.x), s1 = splat2(a4.y);           \
            unsigned long long s2 = splat2(a4.z), s3 = splat2(a4.w);           \
            acc[0] = fma2(wA[KK], s0, acc[0]); acc[1] = fma2(wB[KK], s0, acc[1]);\
            acc[2] = fma2(wA[KK], s1, acc[2]); acc[3] = fma2(wB[KK], s1, acc[3]);\
            acc[4] = fma2(wA[KK], s2, acc[4]); acc[5] = fma2(wB[KK], s2, acc[5]);\
            acc[6] = fma2(wA[KK], s3, acc[6]); acc[7] = fma2(wB[KK], s3, acc[7]);\
        }

    // ---- prologue: own chunks (zeros) + x chunks, on buffer 0 ----
    unsigned long long acc[8];
    #pragma unroll
    for (int i = 0; i < 8; ++i) acc[i] = 0ull;
    {
        const float* aBuf = sA;
        GEMM_STEP(14 * 32 + lane, 14)
        GEMM_STEP(15 * 32 + lane, 15)
        #pragma unroll
        for (int j = 16; j < 20; ++j)
            GEMM_STEP(HDIM + (j - 16) * 32 + lane, j)
    }

    int ph0 = 0, ph1 = 0;
    int cur = 0;
    for (int t = 0; t < T_STEPS; ++t) {
        // ---- wait for 7 peers' fr(t); re-arm for t+2 ----
        if (t > 0) {
            unsigned mb = mbarBase + (unsigned)(cur * 8);
            unsigned par = (unsigned)(cur ? ph1 : ph0);
            mbar_wait_parity(mb, par);
            if (cur) ph1 ^= 1; else ph0 ^= 1;
            if (tid == 0) mbar_arrive_expect_tx(mb, TX_BYTES);
        }

        // prefetch x(t+1) — hidden under main GEMM
        float xv = 0.f;
        if (t + 1 < T_STEPS)
            xv = input[((size_t)(t + 1) * BATCH + b0 + xb) * DDIM + xd];

        const float* aBuf = sA + cur * ABUF_FLOATS;

        // ---- main GEMM: peer chunks 0..13, all-static addressing ----
        #pragma unroll
        for (int j = 0; j < 14; ++j)
            GEMM_STEP(j * 32 + lane, j)

        // ---- unpack + warp butterfly (16 outputs over 32 lanes) ----
        float v[16];
        #pragma unroll
        for (int b = 0; b < 4; ++b) {
            v[0 * 4 + b] = lo32(acc[2 * b]);
            v[1 * 4 + b] = hi32(acc[2 * b]);
            v[2 * 4 + b] = lo32(acc[2 * b + 1]);
            v[3 * 4 + b] = hi32(acc[2 * b + 1]);
        }
        #pragma unroll
        for (int s = 16, cnt = 16; s >= 2; s >>= 1, cnt >>= 1) {
            const bool up = (lane & s) != 0;
            const int half = cnt >> 1;
            #pragma unroll
            for (int i = 0; i < 8; ++i) {
                if (i >= half) break;
                float keep = up ? v[i + half] : v[i];
                float send = up ? v[i] : v[i + half];
                float got  = __shfl_xor_sync(0xFFFFFFFFu, send, s);
                v[i] = keep + got;
            }
        }
        v[0] += __shfl_xor_sync(0xFFFFFFFFu, v[0], 1);

        // ---- leaky update + relu ----
        vreg = (1.0f - ALPHA) * vreg + (v[0] + breg);
        float fr = fmaxf(vreg, 0.f);
        if ((lane & 1) == 0)
            out[((size_t)t * BATCH + b0 + bb) * HDIM + hmine] = fr;

        if (t + 1 < T_STEPS) {
            const int nxt = cur ^ 1;
            float* nbuf = sA + nxt * ABUF_FLOATS;

            // gather 4 batch values per g; write own POSITION-7 slice
            float frb1 = __shfl_xor_sync(0xFFFFFFFFu, fr, 2);
            unsigned long long p01 = pack2(fr, frb1);
            unsigned long long p23 = __shfl_xor_sync(0xFFFFFFFFu, p01, 4);
            if ((lane & 7) == 0) {
                int lg = w * 4 + (lane >> 3);      // local g 0..63
                *(float4*)&nbuf[(448 + lg) * 4] =
                    make_float4(lo32(p01), hi32(p01), lo32(p23), hi32(p23));
            }
            // stage x(t+1)
            nbuf[(HDIM + xd) * 4 + xb] = xv;

            __syncthreads();   // own pos-7 slice + x visible CTA-wide

            // ---- 7 threads push the contiguous 1KB own-slice to 7 peers ----
            if (tid < 7) {
                fence_proxy_async_cta();
                unsigned c = (unsigned)tid + ((tid >= rank) ? 1u : 0u);
                unsigned p = (unsigned)(rank - (int)c - 1) & 7u;   // my pos in peer c
                unsigned src = smemBase
                    + (unsigned)((nxt * ABUF_FLOATS + 448 * 4) * 4);
                unsigned dst = smemBase
                    + (unsigned)((nxt * ABUF_FLOATS + (int)p * 256) * 4);
                unsigned mOff = mbarBase + (unsigned)(nxt * 8);
                bulk_dsmem(mapa_u32(dst, c), src, 1024, mapa_u32(mOff, c));
            }

            // ---- prewait GEMM for t+1: own chunks 14,15 + x 16..19 ----
            // (overlaps fabric flight + peer skew; all data local)
            #pragma unroll
            for (int i = 0; i < 8; ++i) acc[i] = 0ull;
            {
                const float* aBuf = nbuf;
                GEMM_STEP(14 * 32 + lane, 14)
                GEMM_STEP(15 * 32 + lane, 15)
                #pragma unroll
                for (int j = 16; j < 20; ++j)
                    GEMM_STEP(HDIM + (j - 16) * 32 + lane, j)
            }
        }
        cur ^= 1;
    }
}

extern "C" void kernel_launch(void* const* d_in, const int* in_sizes, int n_in,
                              void* d_out, int out_size)
{
    const float* input = (const float*)d_in[0];
    const float* Win   = (const float*)d_in[1];
    const float* bin   = (const float*)d_in[2];
    const float* Whid  = (const float*)d_in[3];
    const float* bhid  = (const float*)d_in[4];
    float* out = (float*)d_out;

    cudaFuncSetAttribute(rnn_kernel,
                         cudaFuncAttributeMaxDynamicSharedMemorySize, SMEM_BYTES);

    cudaLaunchConfig_t cfg = {};
    cfg.gridDim  = dim3(16 * CLUSTER, 1, 1);
    cfg.blockDim = dim3(NTHR, 1, 1);
    cfg.dynamicSmemBytes = SMEM_BYTES;
    cfg.stream = 0;

    cudaLaunchAttribute attr[1];
    attr[0].id = cudaLaunchAttributeClusterDimension;
    attr[0].val.clusterDim.x = CLUSTER;
    attr[0].val.clusterDim.y = 1;
    attr[0].val.clusterDim.z = 1;
    cfg.attrs = attr;
    cfg.numAttrs = 1;

    cudaLaunchKernelEx(&cfg, rnn_kernel, input, Win, bin, Whid, bhid, out);
}

// round 10
// speedup vs baseline: 1.2818x; 1.0002x over previous
#include <cuda_runtime.h>
#include <cstdint>
#include <cstddef>

#define T_STEPS 1024
#define BATCH   64
#define DDIM    128
#define HDIM    512
#define ALPHA   0.1f

#define CLUSTER 8
#define BPC     4
#define NTHR    512

#define ABUF_FLOATS  2560                 // [k(640)][b(4)] ; k<512 fr (8 rotated
                                          // 64-g positions), k>=512 x
#define SA_FLOATS    (2 * ABUF_FLOATS)    // ping-pong
#define MBAR_OFF     SA_FLOATS            // float idx; 4 mbars (buf x {A,B})
#define SMEM_BYTES   ((MBAR_OFF + 16) * 4)

#define TXA_BYTES 4096                    // positions 0..3 (4 near peers x 1KB)
#define TXB_BYTES 3072                    // positions 4..6 (3 far peers x 1KB)

// ---- packed fp32x2 helpers ----
__device__ __forceinline__ unsigned long long fma2(unsigned long long a,
                                                   unsigned long long b,
                                                   unsigned long long c) {
    unsigned long long d;
    asm("fma.rn.f32x2 %0, %1, %2, %3;" : "=l"(d) : "l"(a), "l"(b), "l"(c));
    return d;
}
__device__ __forceinline__ unsigned long long splat2(float x) {
    unsigned long long d;
    asm("mov.b64 %0, {%1, %1};" : "=l"(d) : "f"(x));
    return d;
}
__device__ __forceinline__ unsigned long long pack2(float lo, float hi) {
    unsigned long long d;
    asm("mov.b64 %0, {%1, %2};" : "=l"(d) : "f"(lo), "f"(hi));
    return d;
}
__device__ __forceinline__ float lo32(unsigned long long v) {
    return __uint_as_float((unsigned)(v & 0xFFFFFFFFull));
}
__device__ __forceinline__ float hi32(unsigned long long v) {
    return __uint_as_float((unsigned)(v >> 32));
}

// ---- cluster / mbarrier helpers ----
__device__ __forceinline__ unsigned mapa_u32(unsigned addr, unsigned rank) {
    unsigned d;
    asm("mapa.shared::cluster.u32 %0, %1, %2;" : "=r"(d) : "r"(addr), "r"(rank));
    return d;
}
__device__ __forceinline__ void mbar_init(unsigned addr, unsigned cnt) {
    asm volatile("mbarrier.init.shared.b64 [%0], %1;" :: "r"(addr), "r"(cnt) : "memory");
}
__device__ __forceinline__ void mbar_arrive_expect_tx(unsigned addr, unsigned bytes) {
    asm volatile("mbarrier.arrive.expect_tx.shared.b64 _, [%0], %1;"
                 :: "r"(addr), "r"(bytes) : "memory");
}
__device__ __forceinline__ void mbar_wait_parity(unsigned addr, unsigned parity) {
    unsigned done;
    asm volatile(
        "{\n\t.reg .pred p;\n\t"
        "mbarrier.try_wait.parity.acquire.cta.shared::cta.b64 p, [%1], %2;\n\t"
        "selp.b32 %0, 1, 0, p;\n\t}"
        : "=r"(done) : "r"(addr), "r"(parity) : "memory");
    if (!done) {
        asm volatile(
            "{\n\t.reg .pred P1;\n\t"
            "WAIT_LOOP_%=:\n\t"
            "mbarrier.try_wait.parity.acquire.cta.shared::cta.b64 P1, [%0], %1, 0x989680;\n\t"
            "@P1 bra.uni WAIT_DONE_%=;\n\t"
            "bra.uni WAIT_LOOP_%=;\n\t"
            "WAIT_DONE_%=:\n\t}"
            :: "r"(addr), "r"(parity) : "memory");
    }
}
__device__ __forceinline__ void bulk_dsmem(unsigned dst_cluster, unsigned src_cta,
                                           unsigned bytes, unsigned mbar_cluster) {
    asm volatile(
        "cp.async.bulk.shared::cluster.shared::cta.mbarrier::complete_tx::bytes "
        "[%0], [%1], %2, [%3];"
        :: "r"(dst_cluster), "r"(src_cta), "r"(bytes), "r"(mbar_cluster) : "memory");
}
__device__ __forceinline__ void fence_proxy_async_cta() {
    asm volatile("fence.proxy.async.shared::cta;" ::: "memory");
}
__device__ __forceinline__ void cluster_sync_() {
    asm volatile("barrier.cluster.arrive.aligned;" ::: "memory");
    asm volatile("barrier.cluster.wait.aligned;" ::: "memory");
}

__global__ void __launch_bounds__(NTHR, 1)
rnn_kernel(const float* __restrict__ input, const float* __restrict__ Win,
           const float* __restrict__ bin,   const float* __restrict__ Whid,
           const float* __restrict__ bhid,  float* __restrict__ out)
{
    extern __shared__ float sA[];   // [2][640][4] | mbar[4]

    const int tid  = threadIdx.x;
    const int lane = tid & 31;
    const int w    = tid >> 5;
    const int bx   = blockIdx.x;
    const int rank = bx & (CLUSTER - 1);
    const int cl   = bx >> 3;
    const int b0   = cl * BPC;
    const int g0   = rank * 64;
    const int gbase = g0 + w * 4;

    // lane's output after the butterfly (verified mapping):
    const int vidx = ((lane >> 4) & 1) * 8 + ((lane >> 3) & 1) * 4
                   + ((lane >> 2) & 1) * 2 + ((lane >> 1) & 1);
    const int gl = vidx >> 2;
    const int bb = vidx & 3;
    const int hmine = gbase + gl;

    // ---- W into registers, permuted to ROTATED BUFFER LAYOUT ----
    // Buffer position p (chunks 2p, 2p+1) holds slice of rank (rank+1+p)&7
    // for p<7; position 7 (chunks 14,15) holds OWN slice.
    unsigned long long wA[20], wB[20];
    #pragma unroll
    for (int j = 0; j < 16; ++j) {
        int p  = j >> 1;
        int rr = (p < 7) ? ((rank + 1 + p) & 7) : rank;
        int h  = rr * 64 + (j & 1) * 32 + lane;
        wA[j] = pack2(ALPHA * Whid[(gbase + 0) * HDIM + h],
                      ALPHA * Whid[(gbase + 1) * HDIM + h]);
        wB[j] = pack2(ALPHA * Whid[(gbase + 2) * HDIM + h],
                      ALPHA * Whid[(gbase + 3) * HDIM + h]);
    }
    #pragma unroll
    for (int j = 16; j < 20; ++j) {
        int k = (j - 16) * 32 + lane;
        wA[j] = pack2(ALPHA * Win[(gbase + 0) * DDIM + k],
                      ALPHA * Win[(gbase + 1) * DDIM + k]);
        wB[j] = pack2(ALPHA * Win[(gbase + 2) * DDIM + k],
                      ALPHA * Win[(gbase + 3) * DDIM + k]);
    }
    const float breg = ALPHA * (bhid[hmine] + bin[hmine]);
    float vreg = 0.0f;

    const unsigned smemBase = (unsigned)__cvta_generic_to_shared(sA);
    const unsigned mbarBase = smemBase + MBAR_OFF * 4;
    // mbar layout: [buf0A, buf0B, buf1A, buf1B] x 8 bytes

    // ---- init: buffer0 fr = 0 ; x = input[t=0]; arm all 4 mbars ----
    {
        float4 z = {0.f, 0.f, 0.f, 0.f};
        ((float4*)sA)[tid] = z;
        int d = w * 8 + (lane >> 2);
        int b = lane & 3;
        sA[(HDIM + d) * 4 + b] = input[(size_t)(b0 + b) * DDIM + d];
    }
    if (tid == 0) {
        #pragma unroll
        for (int m = 0; m < 4; ++m) mbar_init(mbarBase + m * 8, 1);
        mbar_arrive_expect_tx(mbarBase + 0,  TXA_BYTES);
        mbar_arrive_expect_tx(mbarBase + 8,  TXB_BYTES);
        mbar_arrive_expect_tx(mbarBase + 16, TXA_BYTES);
        mbar_arrive_expect_tx(mbarBase + 24, TXB_BYTES);
    }
    __syncthreads();
    cluster_sync_();   // mbars live before any peer bulk-copy can land

    const int xd = w * 8 + (lane >> 2);
    const int xb = lane & 3;

    #define GEMM_STEP(KIDX, KK)                                                \
        {                                                                      \
            float4 a4 = *(const float4*)&aBuf[(KIDX) * 4];                     \
            unsigned long long s0 = splat2(a4.x), s1 = splat2(a4.y);           \
            unsigned long long s2 = splat2(a4.z), s3 = splat2(a4.w);           \
            acc[0] = fma2(wA[KK], s0, acc[0]); acc[1] = fma2(wB[KK], s0, acc[1]);\
            acc[2] = fma2(wA[KK], s1, acc[2]); acc[3] = fma2(wB[KK], s1, acc[3]);\
            acc[4] = fma2(wA[KK], s2, acc[4]); acc[5] = fma2(wB[KK], s2, acc[5]);\
            acc[6] = fma2(wA[KK], s3, acc[6]); acc[7] = fma2(wB[KK], s3, acc[7]);\
        }

    // ---- prologue: own chunks (zeros) + x chunks, on buffer 0 ----
    unsigned long long acc[8];
    #pragma unroll
    for (int i = 0; i < 8; ++i) acc[i] = 0ull;
    {
        const float* aBuf = sA;
        GEMM_STEP(14 * 32 + lane, 14)
        GEMM_STEP(15 * 32 + lane, 15)
        #pragma unroll
        for (int j = 16; j < 20; ++j)
            GEMM_STEP(HDIM + (j - 16) * 32 + lane, j)
    }

    // x pipeline: xv_cur = x(t+1) staged during step t (loaded 2 steps ahead)
    float xv_cur = (T_STEPS > 1)
        ? input[((size_t)1 * BATCH + b0 + xb) * DDIM + xd] : 0.f;

    int ph0 = 0, ph1 = 0;
    int cur = 0;
    for (int t = 0; t < T_STEPS; ++t) {
        const unsigned mbA = mbarBase + (unsigned)(cur * 16);
        const unsigned mbB = mbA + 8;
        const unsigned par = (unsigned)(cur ? ph1 : ph0);

        // ---- wait A: near peers (positions 0..3); re-arm for t+2 ----
        if (t > 0) {
            mbar_wait_parity(mbA, par);
            if (tid == 0) mbar_arrive_expect_tx(mbA, TXA_BYTES);
        }

        // prefetch x(t+2) — consumed next step, ~full step of cover
        float xv_next = 0.f;
        if (t + 2 < T_STEPS)
            xv_next = input[((size_t)(t + 2) * BATCH + b0 + xb) * DDIM + xd];

        const float* aBuf = sA + cur * ABUF_FLOATS;

        // ---- GEMM chunks 0..7 (positions 0..3, covered by waitA) ----
        #pragma unroll
        for (int j = 0; j < 8; ++j)
            GEMM_STEP(j * 32 + lane, j)

        // ---- wait B: far peers (positions 4..6); re-arm for t+2 ----
        if (t > 0) {
            mbar_wait_parity(mbB, par);
            if (tid == 0) mbar_arrive_expect_tx(mbB, TXB_BYTES);
            if (cur) ph1 ^= 1; else ph0 ^= 1;
        }

        // ---- GEMM chunks 8..13 ----
        #pragma unroll
        for (int j = 8; j < 14; ++j)
            GEMM_STEP(j * 32 + lane, j)

        // ---- unpack + warp butterfly (16 outputs over 32 lanes) ----
        float v[16];
        #pragma unroll
        for (int b = 0; b < 4; ++b) {
            v[0 * 4 + b] = lo32(acc[2 * b]);
            v[1 * 4 + b] = hi32(acc[2 * b]);
            v[2 * 4 + b] = lo32(acc[2 * b + 1]);
            v[3 * 4 + b] = hi32(acc[2 * b + 1]);
        }
        #pragma unroll
        for (int s = 16, cnt = 16; s >= 2; s >>= 1, cnt >>= 1) {
            const bool up = (lane & s) != 0;
            const int half = cnt >> 1;
            #pragma unroll
            for (int i = 0; i < 8; ++i) {
                if (i >= half) break;
                float keep = up ? v[i + half] : v[i];
                float send = up ? v[i] : v[i + half];
                float got  = __shfl_xor_sync(0xFFFFFFFFu, send, s);
                v[i] = keep + got;
            }
        }
        v[0] += __shfl_xor_sync(0xFFFFFFFFu, v[0], 1);

        // ---- leaky update + relu ----
        vreg = (1.0f - ALPHA) * vreg + (v[0] + breg);
        float fr = fmaxf(vreg, 0.f);
        if ((lane & 1) == 0)
            out[((size_t)t * BATCH + b0 + bb) * HDIM + hmine] = fr;

        if (t + 1 < T_STEPS) {
            const int nxt = cur ^ 1;
            float* nbuf = sA + nxt * ABUF_FLOATS;

            // gather 4 batch values per g; write own POSITION-7 slice
            float frb1 = __shfl_xor_sync(0xFFFFFFFFu, fr, 2);
            unsigned long long p01 = pack2(fr, frb1);
            unsigned long long p23 = __shfl_xor_sync(0xFFFFFFFFu, p01, 4);
            if ((lane & 7) == 0) {
                int lg = w * 4 + (lane >> 3);      // local g 0..63
                *(float4*)&nbuf[(448 + lg) * 4] =
                    make_float4(lo32(p01), hi32(p01), lo32(p23), hi32(p23));
            }
            // stage x(t+1) — value loaded two steps ago, LDG long settled
            nbuf[(HDIM + xd) * 4 + xb] = xv_cur;

            __syncthreads();   // own pos-7 slice + x visible CTA-wide

            // ---- 7 threads push the contiguous 1KB own-slice to 7 peers ----
            // target peer's mbarA if my position there is 0..3, else mbarB
            if (tid < 7) {
                fence_proxy_async_cta();
                unsigned c = (unsigned)tid + ((tid >= rank) ? 1u : 0u);
                unsigned p = (unsigned)(rank - (int)c - 1) & 7u;   // my pos in peer c
                unsigned src = smemBase
                    + (unsigned)((nxt * ABUF_FLOATS + 448 * 4) * 4);
                unsigned dst = smemBase
                    + (unsigned)((nxt * ABUF_FLOATS + (int)p * 256) * 4);
                unsigned mOff = mbarBase + (unsigned)(nxt * 16) + ((p < 4) ? 0u : 8u);
                bulk_dsmem(mapa_u32(dst, c), src, 1024, mapa_u32(mOff, c));
            }

            // ---- prewait GEMM for t+1: own chunks 14,15 + x 16..19 ----
            #pragma unroll
            for (int i = 0; i < 8; ++i) acc[i] = 0ull;
            {
                const float* aBuf = nbuf;
                GEMM_STEP(14 * 32 + lane, 14)
                GEMM_STEP(15 * 32 + lane, 15)
                #pragma unroll
                for (int j = 16; j < 20; ++j)
                    GEMM_STEP(HDIM + (j - 16) * 32 + lane, j)
            }
        }
        xv_cur = xv_next;
        cur ^= 1;
    }
}

extern "C" void kernel_launch(void* const* d_in, const int* in_sizes, int n_in,
                              void* d_out, int out_size)
{
    const float* input = (const float*)d_in[0];
    const float* Win   = (const float*)d_in[1];
    const float* bin   = (const float*)d_in[2];
    const float* Whid  = (const float*)d_in[3];
    const float* bhid  = (const float*)d_in[4];
    float* out = (float*)d_out;

    cudaFuncSetAttribute(rnn_kernel,
                         cudaFuncAttributeMaxDynamicSharedMemorySize, SMEM_BYTES);

    cudaLaunchConfig_t cfg = {};
    cfg.gridDim  = dim3(16 * CLUSTER, 1, 1);
    cfg.blockDim = dim3(NTHR, 1, 1);
    cfg.dynamicSmemBytes = SMEM_BYTES;
    cfg.stream = 0;

    cudaLaunchAttribute attr[1];
    attr[0].id = cudaLaunchAttributeClusterDimension;
    attr[0].val.clusterDim.x = CLUSTER;
    attr[0].val.clusterDim.y = 1;
    attr[0].val.clusterDim.z = 1;
    cfg.attrs = attr;
    cfg.numAttrs = 1;

    cudaLaunchKernelEx(&cfg, rnn_kernel, input, Win, bin, Whid, bhid, out);
}